// round 16
// baseline (speedup 1.0000x reference)
#include <cuda_runtime.h>
#include <cuda_fp16.h>
#include <math.h>
#include <stdint.h>

#define B_ 8192
#define D_ 1024
#define L_ 5
#define H_ 512
#define BD_ (B_ * D_)
#define NC_ 1536                              // merged es(1024)+qg1(512) width

// ================= scratch (device globals; no allocations) =================
__device__ __half g_cur[B_ * D_];
__device__ float  g_buf2d[B_ * 2 * D_];       // pre-LN float (pg1)
__device__ __half g_buf2dh[B_ * 2 * D_];      // GELU(LN) half
__device__ __half g_pat[B_ * D_];
__device__ float  g_tmpc[B_ * NC_];           // merged pre-LN float (es|qg1)
__device__ __half g_tmph[B_ * H_];            // ReLU(LN) half
__device__ float  g_emo[B_ * D_];
__device__ float  g_sl[L_ * B_ * D_];         // per-layer stable (fp32, pure stores)
__device__ __half g_cmat[D_ * D_];            // C[k][n] = 0.9^((n-k)%D)
__device__ __half g_rcp[B_ * D_];
__device__ double g_part[1024];
__device__ float  g_bcomb[L_ * NC_];          // combined es_b | qg_b1
__device__ float  g_sigsc[L_ * D_];           // precomputed sigmoid(stability)
// half weights ([K,N] layout)
__device__ __half g_wpg1[L_ * D_ * 2 * D_];
__device__ __half g_wpg2[L_ * 2 * D_ * D_];
__device__ __half g_wcomb[L_ * D_ * NC_];     // es_w | qg_w1 merged
__device__ __half g_wqg2[L_ * H_ * D_];

enum { ACT_NONE = 0, ACT_TANH_STABLE = 1, ACT_SIGMOID = 2 };

// ================= helpers =================
__device__ __forceinline__ uint32_t smem_u32(const void* p) {
    uint32_t a;
    asm("{ .reg .u64 t; cvta.to.shared.u64 t, %1; cvt.u32.u64 %0, t; }"
        : "=r"(a) : "l"(p));
    return a;
}
__device__ __forceinline__ void cp16(uint32_t dst, const void* src) {
    asm volatile("cp.async.cg.shared.global [%0], [%1], 16;" :: "r"(dst), "l"(src));
}
__device__ __forceinline__ void cp_commit() {
    asm volatile("cp.async.commit_group;" ::: "memory");
}
template <int N>
__device__ __forceinline__ void cp_wait() {
    asm volatile("cp.async.wait_group %0;" :: "n"(N) : "memory");
}
__device__ __forceinline__ void ldm_x4(uint32_t* r, uint32_t addr) {
    asm volatile("ldmatrix.sync.aligned.m8n8.x4.shared.b16 {%0,%1,%2,%3}, [%4];"
                 : "=r"(r[0]), "=r"(r[1]), "=r"(r[2]), "=r"(r[3]) : "r"(addr));
}
__device__ __forceinline__ void ldm_x4_trans(uint32_t* r, uint32_t addr) {
    asm volatile("ldmatrix.sync.aligned.m8n8.x4.trans.shared.b16 {%0,%1,%2,%3}, [%4];"
                 : "=r"(r[0]), "=r"(r[1]), "=r"(r[2]), "=r"(r[3]) : "r"(addr));
}
__device__ __forceinline__ void mma_f16(float* d, const uint32_t* a, const uint32_t* b) {
    asm volatile(
        "mma.sync.aligned.m16n8k16.row.col.f32.f16.f16.f32 "
        "{%0,%1,%2,%3}, {%4,%5,%6,%7}, {%8,%9}, {%0,%1,%2,%3};"
        : "+f"(d[0]), "+f"(d[1]), "+f"(d[2]), "+f"(d[3])
        : "r"(a[0]), "r"(a[1]), "r"(a[2]), "r"(a[3]), "r"(b[0]), "r"(b[1]));
}
// fast sigmoid / tanh via MUFU exp (rel err ~2e-6, negligible vs fp16 path err)
__device__ __forceinline__ float sigmf(float x) { return 1.f / (1.f + __expf(-x)); }
__device__ __forceinline__ float tanhfast(float x) {
    float e = __expf(-2.f * fabsf(x));
    float t = (1.f - e) / (1.f + e);
    return copysignf(t, x);
}

// ================= fp16 tensor-core GEMM (128x128, 3-stage static) =========
#define MT 128
#define NT 128
#define KC 64
#define NTHR 256
#define A_BYTES (MT * KC * 2)                // 16384 (row = 128B)
#define B_BYTES (KC * NT * 2)                // 16384 (row = 256B)
#define STAGE_BYTES (A_BYTES + B_BYTES)      // 32768
#define GEMM_SMEM (3 * STAGE_BYTES)          // 98304 -> 2 CTAs/SM (192KB)

__device__ __forceinline__ void copy_tiles(
    const __half* __restrict__ A, const __half* __restrict__ W, int N, int K,
    int rowBase, int colBase, int k0, uint32_t stageAddr, int tid)
{
#pragma unroll
    for (int j = 0; j < 4; j++) {
        int idx = tid + j * NTHR;
        int r = idx >> 3, c = idx & 7;
        const __half* src = A + (size_t)(rowBase + r) * K + k0 + c * 8;
        uint32_t off = (uint32_t)(r * 128 + c * 16);
        cp16(stageAddr + (off ^ ((off >> 3) & 0x70)), src);
    }
    const uint32_t bAddr = stageAddr + A_BYTES;
#pragma unroll
    for (int j = 0; j < 4; j++) {
        int idx = tid + j * NTHR;
        int kr = idx >> 4, c = idx & 15;
        const __half* src = W + (size_t)(k0 + kr) * N + colBase + c * 8;
        uint32_t off = (uint32_t)(kr * 256 + c * 16);
        cp16(bAddr + (off ^ ((off >> 4) & 0x70)), src);
    }
}

// compute one KC=64 chunk from smem slot at (sb + slotOff); B frags hoisted
__device__ __forceinline__ void compute_chunk(
    float acc[4][4][4], uint32_t sb, uint32_t slotOff,
    int arow0, int bcol0, int lr, int lc16)
{
    const uint32_t aBase = sb + slotOff;
    const uint32_t bBase = aBase + A_BYTES;

    uint32_t bf[4][4][2];
#pragma unroll
    for (int ks = 0; ks < 4; ks++) {
#pragma unroll
        for (int p = 0; p < 2; p++) {
            uint32_t off = (uint32_t)((ks * 16 + lr) * 256 +
                                      (bcol0 + p * 16) * 2 + lc16);
            uint32_t r[4];
            ldm_x4_trans(r, bBase + (off ^ ((off >> 4) & 0x70)));
            bf[ks][2 * p][0] = r[0]; bf[ks][2 * p][1] = r[1];
            bf[ks][2 * p + 1][0] = r[2]; bf[ks][2 * p + 1][1] = r[3];
        }
    }
#pragma unroll
    for (int ks = 0; ks < 4; ks++) {
        uint32_t af[4][4];
#pragma unroll
        for (int mi = 0; mi < 4; mi++) {
            uint32_t off = (uint32_t)((arow0 + mi * 16 + lr) * 128 + ks * 32 + lc16);
            ldm_x4(af[mi], aBase + (off ^ ((off >> 3) & 0x70)));
        }
#pragma unroll
        for (int mi = 0; mi < 4; mi++)
#pragma unroll
            for (int ni = 0; ni < 4; ni++)
                mma_f16(acc[mi][ni], af[mi], bf[ks][ni]);
    }
}

// pipeline step for chunk j: wait, sync, refill slot (j+2)%3 FIRST, compute j
__device__ __forceinline__ void pipe_step(
    const __half* __restrict__ A, const __half* __restrict__ W, int N, int K,
    int rowBase, int colBase, int j, int nk,
    uint32_t computeSlot, uint32_t fillSlot,
    float acc[4][4][4], uint32_t sb, int arow0, int bcol0,
    int lr, int lc16, int tid)
{
    cp_wait<1>();            // chunk j resident (exactly 2 groups outstanding)
    __syncthreads();         // all warps past compute(j-1) -> fill slot is free
    if (j + 2 < nk)
        copy_tiles(A, W, N, K, rowBase, colBase, (j + 2) * KC, sb + fillSlot, tid);
    cp_commit();             // empty group at tail keeps wait counts uniform
    compute_chunk(acc, sb, computeSlot, arow0, bcol0, lr, lc16);
}

// full GEMM body (mainloop + fused epilogue), shared by both wrappers
__device__ __forceinline__ void gemm_body(
    const __half* __restrict__ A, const __half* __restrict__ W,
    const float* __restrict__ bias, float* __restrict__ Cf, __half* __restrict__ Ch,
    int N, int K, int act,
    const float* __restrict__ sigsc, __half* __restrict__ curout,
    float* __restrict__ sl, int bx, uint32_t sb)
{
    const int tid = threadIdx.x;
    const int wid = tid >> 5, lane = tid & 31;
    const int g = lane >> 2, tig = lane & 3;
    const int warp_m = wid & 1;
    const int warp_n = wid >> 1;
    const int rowBase = blockIdx.y * MT;
    const int colBase = bx * NT;
    const int nk = K / KC;

    const int lr = (lane & 7) + ((lane >> 3) & 1) * 8;
    const int lc16 = ((lane >> 4) & 1) * 16;

    float acc[4][4][4];
#pragma unroll
    for (int mi = 0; mi < 4; mi++)
#pragma unroll
        for (int ni = 0; ni < 4; ni++)
#pragma unroll
            for (int q = 0; q < 4; q++) acc[mi][ni][q] = 0.f;

    // prologue: stage chunks 0 -> slot0, 1 -> slot1 (separate groups)
    copy_tiles(A, W, N, K, rowBase, colBase, 0, sb, tid);
    cp_commit();
    if (nk > 1)
        copy_tiles(A, W, N, K, rowBase, colBase, KC, sb + STAGE_BYTES, tid);
    cp_commit();

    const int arow0 = warp_m * 64;
    const int bcol0 = warp_n * 32;

    // unroll-3 with static slot constants; guards handle nk%3 tails
    for (int i = 0; i < nk; i += 3) {
        pipe_step(A, W, N, K, rowBase, colBase, i, nk,
                  0, 2 * STAGE_BYTES, acc, sb, arow0, bcol0, lr, lc16, tid);
        if (i + 1 < nk)
            pipe_step(A, W, N, K, rowBase, colBase, i + 1, nk,
                      STAGE_BYTES, 0, acc, sb, arow0, bcol0, lr, lc16, tid);
        if (i + 2 < nk)
            pipe_step(A, W, N, K, rowBase, colBase, i + 2, nk,
                      2 * STAGE_BYTES, STAGE_BYTES, acc, sb, arow0, bcol0, lr, lc16, tid);
    }

    // ---------------- fused epilogue ----------------
    const bool cf_vec = (((uintptr_t)Cf & 7) == 0);

    float bcol[4][2], gcol[4][2];
    if (act != ACT_SIGMOID) {
#pragma unroll
        for (int ni = 0; ni < 4; ni++) {
            const int c0 = colBase + warp_n * 32 + ni * 8 + tig * 2;
            bcol[ni][0] = bias[c0];
            bcol[ni][1] = bias[c0 + 1];
            if (act == ACT_TANH_STABLE) {
                gcol[ni][0] = sigsc[c0];
                gcol[ni][1] = sigsc[c0 + 1];
            }
        }
    }

#pragma unroll
    for (int mi = 0; mi < 4; mi++) {
        const int r0 = rowBase + warp_m * 64 + mi * 16 + g;
#pragma unroll
        for (int ni = 0; ni < 4; ni++) {
            const int c0 = colBase + warp_n * 32 + ni * 8 + tig * 2;
            float* a4 = acc[mi][ni];
            if (act == ACT_NONE) {
                const float b0 = bcol[ni][0], b1 = bcol[ni][1];
                if (cf_vec) {
                    *(float2*)(Cf + (size_t)r0 * N + c0) =
                        make_float2(a4[0] + b0, a4[1] + b1);
                    *(float2*)(Cf + (size_t)(r0 + 8) * N + c0) =
                        make_float2(a4[2] + b0, a4[3] + b1);
                } else {
                    Cf[(size_t)r0 * N + c0] = a4[0] + b0;
                    Cf[(size_t)r0 * N + c0 + 1] = a4[1] + b1;
                    Cf[(size_t)(r0 + 8) * N + c0] = a4[2] + b0;
                    Cf[(size_t)(r0 + 8) * N + c0 + 1] = a4[3] + b1;
                }
            } else if (act == ACT_SIGMOID) {
                *(float2*)(Cf + (size_t)r0 * N + c0) =
                    make_float2(sigmf(a4[0]), sigmf(a4[1]));
                *(float2*)(Cf + (size_t)(r0 + 8) * N + c0) =
                    make_float2(sigmf(a4[2]), sigmf(a4[3]));
            } else {  // ACT_TANH_STABLE: pure stores only (no RMW)
                const float b0 = bcol[ni][0], b1 = bcol[ni][1];
                const float g0 = gcol[ni][0], g1 = gcol[ni][1];
#pragma unroll
                for (int h = 0; h < 2; h++) {
                    const int row = r0 + h * 8;
                    const size_t idx = (size_t)row * N + c0;
                    float p0 = tanhfast(a4[2 * h] + b0);
                    float p1 = tanhfast(a4[2 * h + 1] + b1);
                    float s0 = p0 * g0, s1 = p1 * g1;
                    *(__half2*)(Ch + idx) = __floats2half2_rn(p0, p1);
                    *(__half2*)(curout + idx) = __floats2half2_rn(s0, s1);
                    *(float2*)(sl + idx) = make_float2(s0, s1);
                }
            }
        }
    }
}

__global__ void __launch_bounds__(NTHR, 2) mma_gemm(
    const __half* __restrict__ A, const __half* __restrict__ W,
    const float* __restrict__ bias, float* __restrict__ Cf, __half* __restrict__ Ch,
    int N, int K, int act,
    const float* __restrict__ sigsc, __half* __restrict__ curout,
    float* __restrict__ sl)
{
    extern __shared__ char smemraw[];
    gemm_body(A, W, bias, Cf, Ch, N, K, act, sigsc, curout, sl,
              blockIdx.x, smem_u32(smemraw));
}

// merged dual-GEMM: blocks [0,nx1) -> problem 1, [nx1, nx1+nx2) -> problem 2
__global__ void __launch_bounds__(NTHR, 2) mma_gemm2(
    const __half* __restrict__ A1, const __half* __restrict__ W1,
    const float* __restrict__ bias1, float* __restrict__ Cf1,
    int N1, int K1, int act1, int nx1,
    const __half* __restrict__ A2, const __half* __restrict__ W2,
    const float* __restrict__ bias2, float* __restrict__ Cf2,
    int N2, int K2, int act2)
{
    extern __shared__ char smemraw[];
    const uint32_t sb = smem_u32(smemraw);
    if ((int)blockIdx.x < nx1)
        gemm_body(A1, W1, bias1, Cf1, nullptr, N1, K1, act1,
                  nullptr, nullptr, nullptr, blockIdx.x, sb);
    else
        gemm_body(A2, W2, bias2, Cf2, nullptr, N2, K2, act2,
                  nullptr, nullptr, nullptr, blockIdx.x - nx1, sb);
}

// ================= LayerNorm + GELU (step 2 only) =================
__global__ void __launch_bounds__(128) ln_gelu_kernel(
    const float* __restrict__ in, const float* __restrict__ g,
    const float* __restrict__ be, __half* __restrict__ outh, int N)
{
    const int row = blockIdx.x;
    const float4* x = (const float4*)(in + (size_t)row * N);
    const int nv = N >> 9;
    float4 v[4];
    float s = 0.f, ss = 0.f;
    for (int t = 0; t < nv; t++) {
        float4 w = x[threadIdx.x + (t << 7)];
        v[t] = w;
        s += w.x + w.y + w.z + w.w;
        ss += w.x * w.x + w.y * w.y + w.z * w.z + w.w * w.w;
    }
#pragma unroll
    for (int o = 16; o > 0; o >>= 1) {
        s += __shfl_down_sync(0xffffffff, s, o);
        ss += __shfl_down_sync(0xffffffff, ss, o);
    }
    __shared__ float sm[8];
    __shared__ float s_mean, s_rstd;
    const int w4 = threadIdx.x >> 5, lane = threadIdx.x & 31;
    if (lane == 0) { sm[w4] = s; sm[4 + w4] = ss; }
    __syncthreads();
    if (threadIdx.x == 0) {
        float S = sm[0] + sm[1] + sm[2] + sm[3];
        float SS = sm[4] + sm[5] + sm[6] + sm[7];
        float m = S / (float)N;
        s_mean = m;
        s_rstd = rsqrtf(SS / (float)N - m * m + 1e-5f);
    }
    __syncthreads();
    const float m = s_mean, r = s_rstd;
    const float k = 0.70710678118654752f;
    for (int t = 0; t < nv; t++) {
        const int c = (threadIdx.x + (t << 7)) << 2;
        float4 gg = *(const float4*)(g + c);
        float4 bb = *(const float4*)(be + c);
        float o0 = (v[t].x - m) * r * gg.x + bb.x;
        float o1 = (v[t].y - m) * r * gg.y + bb.y;
        float o2 = (v[t].z - m) * r * gg.z + bb.z;
        float o3 = (v[t].w - m) * r * gg.w + bb.w;
        o0 = 0.5f * o0 * (1.f + erff(o0 * k));
        o1 = 0.5f * o1 * (1.f + erff(o1 * k));
        o2 = 0.5f * o2 * (1.f + erff(o2 * k));
        o3 = 0.5f * o3 * (1.f + erff(o3 * k));
        const size_t idx = (size_t)row * N + c;
        *(__half2*)(outh + idx) = __floats2half2_rn(o0, o1);
        *(__half2*)(outh + idx + 2) = __floats2half2_rn(o2, o3);
    }
}

// ========== Dual LN: blocks [0,B) -> emo sigmoid-accum (N=1024, off 0);
//                     blocks [B,2B) -> ReLU->half (N=512, off 1024) ==========
__global__ void __launch_bounds__(128) ln_dual_kernel(
    const float* __restrict__ tmpc,
    const float* __restrict__ esg, const float* __restrict__ esbe,
    float* __restrict__ emo, int initFlag,
    const float* __restrict__ qgg, const float* __restrict__ qgbe,
    __half* __restrict__ tmph)
{
    const bool emoPart = (blockIdx.x < B_);
    const int row = emoPart ? blockIdx.x : blockIdx.x - B_;
    const int N = emoPart ? D_ : H_;
    const int off = emoPart ? 0 : D_;
    const float* g = emoPart ? esg : qgg;
    const float* be = emoPart ? esbe : qgbe;

    const float4* x = (const float4*)(tmpc + (size_t)row * NC_ + off);
    const int nv = N >> 9;
    float4 v[2];
    float s = 0.f, ss = 0.f;
    for (int t = 0; t < nv; t++) {
        float4 w = x[threadIdx.x + (t << 7)];
        v[t] = w;
        s += w.x + w.y + w.z + w.w;
        ss += w.x * w.x + w.y * w.y + w.z * w.z + w.w * w.w;
    }
#pragma unroll
    for (int o = 16; o > 0; o >>= 1) {
        s += __shfl_down_sync(0xffffffff, s, o);
        ss += __shfl_down_sync(0xffffffff, ss, o);
    }
    __shared__ float sm[8];
    __shared__ float s_mean, s_rstd;
    const int w4 = threadIdx.x >> 5, lane = threadIdx.x & 31;
    if (lane == 0) { sm[w4] = s; sm[4 + w4] = ss; }
    __syncthreads();
    if (threadIdx.x == 0) {
        float S = sm[0] + sm[1] + sm[2] + sm[3];
        float SS = sm[4] + sm[5] + sm[6] + sm[7];
        float m = S / (float)N;
        s_mean = m;
        s_rstd = rsqrtf(SS / (float)N - m * m + 1e-5f);
    }
    __syncthreads();
    const float m = s_mean, r = s_rstd;
    for (int t = 0; t < nv; t++) {
        const int c = (threadIdx.x + (t << 7)) << 2;
        float4 gg = *(const float4*)(g + c);
        float4 bb = *(const float4*)(be + c);
        float o0 = (v[t].x - m) * r * gg.x + bb.x;
        float o1 = (v[t].y - m) * r * gg.y + bb.y;
        float o2 = (v[t].z - m) * r * gg.z + bb.z;
        float o3 = (v[t].w - m) * r * gg.w + bb.w;
        const size_t idx = (size_t)row * N + c;
        if (emoPart) {
            float4 a;
            a.x = sigmf(o0); a.y = sigmf(o1); a.z = sigmf(o2); a.w = sigmf(o3);
            if (!initFlag) {
                float4 p = *(float4*)(emo + idx);
                a.x += p.x; a.y += p.y; a.z += p.z; a.w += p.w;
            }
            *(float4*)(emo + idx) = a;
        } else {
            o0 = fmaxf(o0, 0.f); o1 = fmaxf(o1, 0.f);
            o2 = fmaxf(o2, 0.f); o3 = fmaxf(o3, 0.f);
            *(__half2*)(tmph + idx) = __floats2half2_rn(o0, o1);
            *(__half2*)(tmph + idx + 2) = __floats2half2_rn(o2, o3);
        }
    }
}

// ========== fused init: seed->half, cmat, bcomb, sigsc, weight conversions ==
__global__ void __launch_bounds__(256) init_kernel(
    const float4* __restrict__ seed4, __half* __restrict__ cur,
    __half* __restrict__ cmat, float* __restrict__ bcomb,
    const float* __restrict__ esb, const float* __restrict__ qgb1,
    const float* __restrict__ sc, float* __restrict__ sigsc,
    const float4* __restrict__ s1, __half* __restrict__ d1, int n1v,
    const float4* __restrict__ s2, __half* __restrict__ d2, int n2v,
    const float* __restrict__ esw, const float* __restrict__ qgw1,
    __half* __restrict__ comb,
    const float4* __restrict__ s5, __half* __restrict__ d5, int n5v)
{
    const int stride = gridDim.x * 256;
    const int t0 = blockIdx.x * 256 + threadIdx.x;
    for (int i = t0; i < BD_ / 4; i += stride) {
        float4 v = seed4[i];
        *(__half2*)(cur + 4 * (size_t)i) = __floats2half2_rn(v.x, v.y);
        *(__half2*)(cur + 4 * (size_t)i + 2) = __floats2half2_rn(v.z, v.w);
    }
    for (int i = t0; i < D_ * D_; i += stride) {
        int k = i >> 10, n = i & (D_ - 1);
        int e = (n - k + D_) & (D_ - 1);
        cmat[i] = __float2half_rn(powf(0.9f, (float)e));
    }
    for (int i = t0; i < L_ * NC_; i += stride) {
        int l = i / NC_, c = i % NC_;
        bcomb[i] = (c < 1024) ? esb[l * 1024 + c] : qgb1[l * 512 + (c - 1024)];
    }
    for (int i = t0; i < L_ * D_; i += stride)
        sigsc[i] = 1.f / (1.f + expf(-sc[i]));
    for (int i = t0; i < n1v; i += stride) {
        float4 v = s1[i];
        *(__half2*)(d1 + 4 * (size_t)i) = __floats2half2_rn(v.x, v.y);
        *(__half2*)(d1 + 4 * (size_t)i + 2) = __floats2half2_rn(v.z, v.w);
    }
    for (int i = t0; i < n2v; i += stride) {
        float4 v = s2[i];
        *(__half2*)(d2 + 4 * (size_t)i) = __floats2half2_rn(v.x, v.y);
        *(__half2*)(d2 + 4 * (size_t)i + 2) = __floats2half2_rn(v.z, v.w);
    }
    for (int i = t0; i < n5v; i += stride) {
        float4 v = s5[i];
        *(__half2*)(d5 + 4 * (size_t)i) = __floats2half2_rn(v.x, v.y);
        *(__half2*)(d5 + 4 * (size_t)i + 2) = __floats2half2_rn(v.z, v.w);
    }
    const int ncomb4 = L_ * D_ * (NC_ / 4);
    for (int i = t0; i < ncomb4; i += stride) {
        int lk = i / (NC_ / 4);
        int n = (i % (NC_ / 4)) << 2;
        float4 v;
        if (n < 1024)
            v = *(const float4*)(esw + (size_t)lk * 1024 + n);
        else
            v = *(const float4*)(qgw1 + (size_t)lk * 512 + (n - 1024));
        __half* dst = comb + (size_t)lk * NC_ + n;
        *(__half2*)dst = __floats2half2_rn(v.x, v.y);
        *(__half2*)(dst + 2) = __floats2half2_rn(v.z, v.w);
    }
}

// ========== fused finalize + stability partial (reads 5 per-layer s arrays) =
__global__ void __launch_bounds__(256) finstab_kernel(
    const float4* __restrict__ s0a, const float4* __restrict__ s1a,
    const float4* __restrict__ s2a, const float4* __restrict__ s3a,
    const float4* __restrict__ s4a,
    const float4* __restrict__ es, float* __restrict__ out,
    __half* __restrict__ rcp, double* __restrict__ part)
{
    double acc = 0.0;
    for (int i = blockIdx.x * 256 + threadIdx.x; i < BD_ / 4; i += gridDim.x * 256) {
        float4 a = s0a[i], b = s1a[i], c = s2a[i], d = s3a[i], f = s4a[i];
        float4 e = es[i];
        float4 p, q;
        p.x = (((a.x + b.x) + c.x) + d.x) + f.x;
        p.y = (((a.y + b.y) + c.y) + d.y) + f.y;
        p.z = (((a.z + b.z) + c.z) + d.z) + f.z;
        p.w = (((a.w + b.w) + c.w) + d.w) + f.w;
        q.x = (((a.x * a.x + b.x * b.x) + c.x * c.x) + d.x * d.x) + f.x * f.x;
        q.y = (((a.y * a.y + b.y * b.y) + c.y * c.y) + d.y * d.y) + f.y * f.y;
        q.z = (((a.z * a.z + b.z * b.z) + c.z * c.z) + d.z * d.z) + f.z * f.z;
        q.w = (((a.w * a.w + b.w * b.w) + c.w * c.w) + d.w * d.w) + f.w * f.w;

        float4 cp = make_float4(p.x * 0.2f, p.y * 0.2f, p.z * 0.2f, p.w * 0.2f);
        *(float4*)(out + 4 * (size_t)i) = cp;
        *(float4*)(out + (size_t)BD_ + 4 * (size_t)i) =
            make_float4(e.x * 0.2f, e.y * 0.2f, e.z * 0.2f, e.w * 0.2f);
        *(__half2*)(rcp + 4 * (size_t)i) = __floats2half2_rn(cp.x, cp.y);
        *(__half2*)(rcp + 4 * (size_t)i + 2) = __floats2half2_rn(cp.z, cp.w);
        acc += (double)((q.x - p.x * p.x * 0.2f) * 0.25f);
        acc += (double)((q.y - p.y * p.y * 0.2f) * 0.25f);
        acc += (double)((q.z - p.z * p.z * 0.2f) * 0.25f);
        acc += (double)((q.w - p.w * p.w * 0.2f) * 0.25f);
    }
#pragma unroll
    for (int o = 16; o > 0; o >>= 1)
        acc += __shfl_down_sync(0xffffffff, acc, o);
    __shared__ double sm[8];
    int w = threadIdx.x >> 5, lane = threadIdx.x & 31;
    if (lane == 0) sm[w] = acc;
    __syncthreads();
    if (threadIdx.x == 0) {
        double t = 0.0;
        for (int i = 0; i < 8; i++) t += sm[i];
        part[blockIdx.x] = t;
    }
}

__global__ void __launch_bounds__(256) stab_final_kernel(const double* __restrict__ part,
                                                         float* __restrict__ out) {
    double acc = 0.0;
    for (int i = threadIdx.x; i < 1024; i += 256) acc += part[i];
#pragma unroll
    for (int o = 16; o > 0; o >>= 1)
        acc += __shfl_down_sync(0xffffffff, acc, o);
    __shared__ double sm[8];
    int w = threadIdx.x >> 5, lane = threadIdx.x & 31;
    if (lane == 0) sm[w] = acc;
    __syncthreads();
    if (threadIdx.x == 0) {
        double t = 0.0;
        for (int i = 0; i < 8; i++) t += sm[i];
        out[0] = (float)(1.0 - t / (double)BD_);
    }
}

// ================= host launch =================
static inline void launch_gemm(const __half* A, const __half* W, const float* bias,
                               float* Cf, __half* Ch, int N, int K, int act,
                               const float* sigsc, __half* curout, float* sl) {
    dim3 grid(N / NT, B_ / MT);
    mma_gemm<<<grid, NTHR, GEMM_SMEM>>>(A, W, bias, Cf, Ch, N, K, act,
                                        sigsc, curout, sl);
}

static inline void launch_gemm2(const __half* A1, const __half* W1, const float* b1,
                                float* C1, int N1, int K1, int act1,
                                const __half* A2, const __half* W2, const float* b2,
                                float* C2, int N2, int K2, int act2) {
    const int nx1 = N1 / NT, nx2 = N2 / NT;
    dim3 grid(nx1 + nx2, B_ / MT);
    mma_gemm2<<<grid, NTHR, GEMM_SMEM>>>(A1, W1, b1, C1, N1, K1, act1, nx1,
                                         A2, W2, b2, C2, N2, K2, act2);
}

extern "C" void kernel_launch(void* const* d_in, const int* in_sizes, int n_in,
                              void* d_out, int out_size)
{
    const float* seed = (const float*)d_in[0];
    const int o = (in_sizes[1] == 1) ? 2 : 1;
    const float* pg_w1 = (const float*)d_in[o + 0];
    const float* pg_b1 = (const float*)d_in[o + 1];
    const float* pg_g1 = (const float*)d_in[o + 2];
    const float* pg_be1 = (const float*)d_in[o + 3];
    const float* pg_w2 = (const float*)d_in[o + 4];
    const float* pg_b2 = (const float*)d_in[o + 5];
    const float* es_w = (const float*)d_in[o + 6];
    const float* es_b = (const float*)d_in[o + 7];
    const float* es_g = (const float*)d_in[o + 8];
    const float* es_be = (const float*)d_in[o + 9];
    const float* qg_w1 = (const float*)d_in[o + 10];
    const float* qg_b1 = (const float*)d_in[o + 11];
    const float* qg_g1 = (const float*)d_in[o + 12];
    const float* qg_be1 = (const float*)d_in[o + 13];
    const float* qg_w2 = (const float*)d_in[o + 14];
    const float* qg_b2 = (const float*)d_in[o + 15];
    const float* sc = (const float*)d_in[o + 16];
    float* out = (float*)d_out;

    __half *cur, *buf2dh, *pat, *tmph, *cmat, *rcp;
    __half *wpg1, *wpg2, *wcomb, *wqg2;
    float *buf2d, *tmpc, *emo, *sl, *bcomb, *sigsc;
    double* part;
    cudaGetSymbolAddress((void**)&cur, g_cur);
    cudaGetSymbolAddress((void**)&buf2d, g_buf2d);
    cudaGetSymbolAddress((void**)&buf2dh, g_buf2dh);
    cudaGetSymbolAddress((void**)&pat, g_pat);
    cudaGetSymbolAddress((void**)&tmpc, g_tmpc);
    cudaGetSymbolAddress((void**)&tmph, g_tmph);
    cudaGetSymbolAddress((void**)&emo, g_emo);
    cudaGetSymbolAddress((void**)&sl, g_sl);
    cudaGetSymbolAddress((void**)&cmat, g_cmat);
    cudaGetSymbolAddress((void**)&rcp, g_rcp);
    cudaGetSymbolAddress((void**)&part, g_part);
    cudaGetSymbolAddress((void**)&bcomb, g_bcomb);
    cudaGetSymbolAddress((void**)&sigsc, g_sigsc);
    cudaGetSymbolAddress((void**)&wpg1, g_wpg1);
    cudaGetSymbolAddress((void**)&wpg2, g_wpg2);
    cudaGetSymbolAddress((void**)&wcomb, g_wcomb);
    cudaGetSymbolAddress((void**)&wqg2, g_wqg2);

    cudaFuncSetAttribute(mma_gemm, cudaFuncAttributeMaxDynamicSharedMemorySize, GEMM_SMEM);
    cudaFuncSetAttribute(mma_gemm2, cudaFuncAttributeMaxDynamicSharedMemorySize, GEMM_SMEM);

    const size_t BD = (size_t)BD_;
    float* out_cf = out + 2 * BD;
    float* out_ss = out + 3 * BD;
    float* out_qa = out + 3 * BD + 1;

    init_kernel<<<4096, 256>>>(
        (const float4*)seed, cur, cmat, bcomb, es_b, qg_b1, sc, sigsc,
        (const float4*)pg_w1, wpg1, L_ * D_ * 2 * D_ / 4,
        (const float4*)pg_w2, wpg2, L_ * 2 * D_ * D_ / 4,
        es_w, qg_w1, wcomb,
        (const float4*)qg_w2, wqg2, L_ * H_ * D_ / 4);

    // layer-0 GEMM1 (standalone)
    launch_gemm(cur, wpg1, pg_b1, buf2d, nullptr, 2 * D_, D_, ACT_NONE,
                nullptr, nullptr, nullptr);

    for (int l = 0; l < L_; l++) {
        // 2) h = GELU(LN(pre1)) -> half
        ln_gelu_kernel<<<B_, 128>>>(buf2d, pg_g1 + (size_t)l * 2 * D_,
                                    pg_be1 + (size_t)l * 2 * D_, buf2dh, 2 * D_);
        // 3) pat = tanh(h @ pg_w2 + b2); stable -> cur (half) + sl[l] (fp32 store)
        launch_gemm(buf2dh, wpg2 + (size_t)l * 2 * D_ * D_, pg_b2 + (size_t)l * D_,
                    nullptr, pat, D_, 2 * D_, ACT_TANH_STABLE,
                    sigsc + (size_t)l * D_, cur, sl + (size_t)l * BD);
        // 4+6 merged) tmpc = pat @ [es_w|qg_w1] + [es_b|qg_b1]   [B,1536] float
        launch_gemm(pat, wcomb + (size_t)l * D_ * NC_, bcomb + (size_t)l * NC_,
                    tmpc, nullptr, NC_, D_, ACT_NONE, nullptr, nullptr, nullptr);
        // 5+7 merged) emo-LN (sigmoid accum) + ReLU-LN -> tmph, one launch
        ln_dual_kernel<<<2 * B_, 128>>>(tmpc,
                                        es_g + (size_t)l * D_, es_be + (size_t)l * D_,
                                        emo, (l == 0),
                                        qg_g1 + (size_t)l * H_, qg_be1 + (size_t)l * H_,
                                        tmph);
        if (l + 1 < L_) {
            // 8) anchors[l]  MERGED WITH  1) pre1 = cur @ pg_w1[l+1] + b1
            launch_gemm2(tmph, wqg2 + (size_t)l * H_ * D_, qg_b2 + (size_t)l * D_,
                         out_qa + (size_t)l * BD, D_, H_, ACT_NONE,
                         cur, wpg1 + (size_t)(l + 1) * D_ * 2 * D_,
                         pg_b1 + (size_t)(l + 1) * 2 * D_, buf2d,
                         2 * D_, D_, ACT_NONE);
        }
    }

    // finalize + stability partials (needs sl[4] from GEMM3(4) and emo)
    finstab_kernel<<<1024, 256>>>(
        (const float4*)(sl + 0 * BD), (const float4*)(sl + 1 * BD),
        (const float4*)(sl + 2 * BD), (const float4*)(sl + 3 * BD),
        (const float4*)(sl + 4 * BD),
        (const float4*)emo, out, rcp, part);
    // anchors[4] MERGED WITH coherence_field = sigmoid(rcp @ C)
    launch_gemm2(tmph, wqg2 + (size_t)4 * H_ * D_, qg_b2 + (size_t)4 * D_,
                 out_qa + (size_t)4 * BD, D_, H_, ACT_NONE,
                 rcp, cmat, nullptr, out_cf, D_, D_, ACT_SIGMOID);
    stab_final_kernel<<<1, 256>>>(part, out_ss);
    (void)n_in; (void)out_size;
}

// round 17
// speedup vs baseline: 1.0167x; 1.0167x over previous
#include <cuda_runtime.h>
#include <cuda_fp16.h>
#include <math.h>
#include <stdint.h>

#define B_ 8192
#define D_ 1024
#define L_ 5
#define H_ 512
#define BD_ (B_ * D_)
#define NC_ 1536                              // merged es(1024)+qg1(512) width

// ================= scratch (device globals; no allocations) =================
__device__ __half g_cur[B_ * D_];
__device__ float  g_buf2d[B_ * 2 * D_];       // pre-LN float (pg1)
__device__ __half g_buf2dh[B_ * 2 * D_];      // GELU(LN) half
__device__ __half g_pat[B_ * D_];
__device__ float  g_tmpc[B_ * NC_];           // merged pre-LN float (es|qg1)
__device__ __half g_tmph[B_ * H_];            // ReLU(LN) half
__device__ float  g_emo[B_ * D_];
__device__ float  g_sl[L_ * B_ * D_];         // per-layer stable (fp32, pure stores)
__device__ __half g_cmat[D_ * D_];            // C[k][n] = 0.9^((n-k)%D)
__device__ __half g_rcp[B_ * D_];
__device__ double g_part[1024];
__device__ float  g_bcomb[L_ * NC_];          // combined es_b | qg_b1
__device__ float  g_sigsc[L_ * D_];           // precomputed sigmoid(stability)
// half weights ([K,N] layout)
__device__ __half g_wpg1[L_ * D_ * 2 * D_];
__device__ __half g_wpg2[L_ * 2 * D_ * D_];
__device__ __half g_wcomb[L_ * D_ * NC_];     // es_w | qg_w1 merged
__device__ __half g_wqg2[L_ * H_ * D_];

enum { ACT_NONE = 0, ACT_TANH_STABLE = 1, ACT_SIGMOID = 2 };

// ================= helpers =================
__device__ __forceinline__ uint32_t smem_u32(const void* p) {
    uint32_t a;
    asm("{ .reg .u64 t; cvta.to.shared.u64 t, %1; cvt.u32.u64 %0, t; }"
        : "=r"(a) : "l"(p));
    return a;
}
__device__ __forceinline__ void cp16(uint32_t dst, const void* src) {
    asm volatile("cp.async.cg.shared.global [%0], [%1], 16;" :: "r"(dst), "l"(src));
}
__device__ __forceinline__ void cp_commit() {
    asm volatile("cp.async.commit_group;" ::: "memory");
}
template <int N>
__device__ __forceinline__ void cp_wait() {
    asm volatile("cp.async.wait_group %0;" :: "n"(N) : "memory");
}
__device__ __forceinline__ void ldm_x4(uint32_t* r, uint32_t addr) {
    asm volatile("ldmatrix.sync.aligned.m8n8.x4.shared.b16 {%0,%1,%2,%3}, [%4];"
                 : "=r"(r[0]), "=r"(r[1]), "=r"(r[2]), "=r"(r[3]) : "r"(addr));
}
__device__ __forceinline__ void ldm_x4_trans(uint32_t* r, uint32_t addr) {
    asm volatile("ldmatrix.sync.aligned.m8n8.x4.trans.shared.b16 {%0,%1,%2,%3}, [%4];"
                 : "=r"(r[0]), "=r"(r[1]), "=r"(r[2]), "=r"(r[3]) : "r"(addr));
}
__device__ __forceinline__ void mma_f16(float* d, const uint32_t* a, const uint32_t* b) {
    asm volatile(
        "mma.sync.aligned.m16n8k16.row.col.f32.f16.f16.f32 "
        "{%0,%1,%2,%3}, {%4,%5,%6,%7}, {%8,%9}, {%0,%1,%2,%3};"
        : "+f"(d[0]), "+f"(d[1]), "+f"(d[2]), "+f"(d[3])
        : "r"(a[0]), "r"(a[1]), "r"(a[2]), "r"(a[3]), "r"(b[0]), "r"(b[1]));
}
// fast sigmoid / tanh via MUFU exp (rel err ~2e-6, negligible vs fp16 path err)
__device__ __forceinline__ float sigmf(float x) { return 1.f / (1.f + __expf(-x)); }
__device__ __forceinline__ float tanhfast(float x) {
    float e = __expf(-2.f * fabsf(x));
    float t = (1.f - e) / (1.f + e);
    return copysignf(t, x);
}

// ================= fp16 tensor-core GEMM (128x128, 3-stage static) =========
#define MT 128
#define NT 128
#define KC 64
#define NTHR 256
#define A_BYTES (MT * KC * 2)                // 16384 (row = 128B)
#define B_BYTES (KC * NT * 2)                // 16384 (row = 256B)
#define STAGE_BYTES (A_BYTES + B_BYTES)      // 32768
#define GEMM_SMEM (3 * STAGE_BYTES)          // 98304 -> 2 CTAs/SM (192KB)

__device__ __forceinline__ void copy_tiles(
    const __half* __restrict__ A, const __half* __restrict__ W, int N, int K,
    int rowBase, int colBase, int k0, uint32_t stageAddr, int tid)
{
#pragma unroll
    for (int j = 0; j < 4; j++) {
        int idx = tid + j * NTHR;
        int r = idx >> 3, c = idx & 7;
        const __half* src = A + (size_t)(rowBase + r) * K + k0 + c * 8;
        uint32_t off = (uint32_t)(r * 128 + c * 16);
        cp16(stageAddr + (off ^ ((off >> 3) & 0x70)), src);
    }
    const uint32_t bAddr = stageAddr + A_BYTES;
#pragma unroll
    for (int j = 0; j < 4; j++) {
        int idx = tid + j * NTHR;
        int kr = idx >> 4, c = idx & 15;
        const __half* src = W + (size_t)(k0 + kr) * N + colBase + c * 8;
        uint32_t off = (uint32_t)(kr * 256 + c * 16);
        cp16(bAddr + (off ^ ((off >> 4) & 0x70)), src);
    }
}

// compute one KC=64 chunk from smem slot at (sb + slotOff); B frags hoisted
__device__ __forceinline__ void compute_chunk(
    float acc[4][4][4], uint32_t sb, uint32_t slotOff,
    int arow0, int bcol0, int lr, int lc16)
{
    const uint32_t aBase = sb + slotOff;
    const uint32_t bBase = aBase + A_BYTES;

    uint32_t bf[4][4][2];
#pragma unroll
    for (int ks = 0; ks < 4; ks++) {
#pragma unroll
        for (int p = 0; p < 2; p++) {
            uint32_t off = (uint32_t)((ks * 16 + lr) * 256 +
                                      (bcol0 + p * 16) * 2 + lc16);
            uint32_t r[4];
            ldm_x4_trans(r, bBase + (off ^ ((off >> 4) & 0x70)));
            bf[ks][2 * p][0] = r[0]; bf[ks][2 * p][1] = r[1];
            bf[ks][2 * p + 1][0] = r[2]; bf[ks][2 * p + 1][1] = r[3];
        }
    }
#pragma unroll
    for (int ks = 0; ks < 4; ks++) {
        uint32_t af[4][4];
#pragma unroll
        for (int mi = 0; mi < 4; mi++) {
            uint32_t off = (uint32_t)((arow0 + mi * 16 + lr) * 128 + ks * 32 + lc16);
            ldm_x4(af[mi], aBase + (off ^ ((off >> 3) & 0x70)));
        }
#pragma unroll
        for (int mi = 0; mi < 4; mi++)
#pragma unroll
            for (int ni = 0; ni < 4; ni++)
                mma_f16(acc[mi][ni], af[mi], bf[ks][ni]);
    }
}

// pipeline step for chunk j: wait, sync, compute j, THEN refill slot (j+2)%3
__device__ __forceinline__ void pipe_step(
    const __half* __restrict__ A, const __half* __restrict__ W, int N, int K,
    int rowBase, int colBase, int j, int nk,
    uint32_t computeSlot, uint32_t fillSlot,
    float acc[4][4][4], uint32_t sb, int arow0, int bcol0,
    int lr, int lc16, int tid)
{
    cp_wait<1>();            // chunk j resident (exactly 2 groups outstanding)
    __syncthreads();         // all warps past compute(j-1) -> fill slot is free
    compute_chunk(acc, sb, computeSlot, arow0, bcol0, lr, lc16);
    if (j + 2 < nk)
        copy_tiles(A, W, N, K, rowBase, colBase, (j + 2) * KC, sb + fillSlot, tid);
    cp_commit();             // empty group at tail keeps wait counts uniform
}

// full GEMM body (mainloop + fused epilogue), shared by both wrappers
__device__ __forceinline__ void gemm_body(
    const __half* __restrict__ A, const __half* __restrict__ W,
    const float* __restrict__ bias, float* __restrict__ Cf, __half* __restrict__ Ch,
    int N, int K, int act,
    const float* __restrict__ sigsc, __half* __restrict__ curout,
    float* __restrict__ sl, int bx, uint32_t sb)
{
    const int tid = threadIdx.x;
    const int wid = tid >> 5, lane = tid & 31;
    const int g = lane >> 2, tig = lane & 3;
    const int warp_m = wid & 1;
    const int warp_n = wid >> 1;
    const int rowBase = blockIdx.y * MT;
    const int colBase = bx * NT;
    const int nk = K / KC;

    const int lr = (lane & 7) + ((lane >> 3) & 1) * 8;
    const int lc16 = ((lane >> 4) & 1) * 16;

    float acc[4][4][4];
#pragma unroll
    for (int mi = 0; mi < 4; mi++)
#pragma unroll
        for (int ni = 0; ni < 4; ni++)
#pragma unroll
            for (int q = 0; q < 4; q++) acc[mi][ni][q] = 0.f;

    // prologue: stage chunks 0 -> slot0, 1 -> slot1 (separate groups)
    copy_tiles(A, W, N, K, rowBase, colBase, 0, sb, tid);
    cp_commit();
    if (nk > 1)
        copy_tiles(A, W, N, K, rowBase, colBase, KC, sb + STAGE_BYTES, tid);
    cp_commit();

    const int arow0 = warp_m * 64;
    const int bcol0 = warp_n * 32;

    // unroll-3 with static slot constants; guards handle nk%3 tails
    for (int i = 0; i < nk; i += 3) {
        pipe_step(A, W, N, K, rowBase, colBase, i, nk,
                  0, 2 * STAGE_BYTES, acc, sb, arow0, bcol0, lr, lc16, tid);
        if (i + 1 < nk)
            pipe_step(A, W, N, K, rowBase, colBase, i + 1, nk,
                      STAGE_BYTES, 0, acc, sb, arow0, bcol0, lr, lc16, tid);
        if (i + 2 < nk)
            pipe_step(A, W, N, K, rowBase, colBase, i + 2, nk,
                      2 * STAGE_BYTES, STAGE_BYTES, acc, sb, arow0, bcol0, lr, lc16, tid);
    }

    // ---------------- fused epilogue ----------------
    const bool cf_vec = (((uintptr_t)Cf & 7) == 0);

    float bcol[4][2], gcol[4][2];
    if (act != ACT_SIGMOID) {
#pragma unroll
        for (int ni = 0; ni < 4; ni++) {
            const int c0 = colBase + warp_n * 32 + ni * 8 + tig * 2;
            bcol[ni][0] = bias[c0];
            bcol[ni][1] = bias[c0 + 1];
            if (act == ACT_TANH_STABLE) {
                gcol[ni][0] = sigsc[c0];
                gcol[ni][1] = sigsc[c0 + 1];
            }
        }
    }

#pragma unroll
    for (int mi = 0; mi < 4; mi++) {
        const int r0 = rowBase + warp_m * 64 + mi * 16 + g;
#pragma unroll
        for (int ni = 0; ni < 4; ni++) {
            const int c0 = colBase + warp_n * 32 + ni * 8 + tig * 2;
            float* a4 = acc[mi][ni];
            if (act == ACT_NONE) {
                const float b0 = bcol[ni][0], b1 = bcol[ni][1];
                if (cf_vec) {
                    *(float2*)(Cf + (size_t)r0 * N + c0) =
                        make_float2(a4[0] + b0, a4[1] + b1);
                    *(float2*)(Cf + (size_t)(r0 + 8) * N + c0) =
                        make_float2(a4[2] + b0, a4[3] + b1);
                } else {
                    Cf[(size_t)r0 * N + c0] = a4[0] + b0;
                    Cf[(size_t)r0 * N + c0 + 1] = a4[1] + b1;
                    Cf[(size_t)(r0 + 8) * N + c0] = a4[2] + b0;
                    Cf[(size_t)(r0 + 8) * N + c0 + 1] = a4[3] + b1;
                }
            } else if (act == ACT_SIGMOID) {
                *(float2*)(Cf + (size_t)r0 * N + c0) =
                    make_float2(sigmf(a4[0]), sigmf(a4[1]));
                *(float2*)(Cf + (size_t)(r0 + 8) * N + c0) =
                    make_float2(sigmf(a4[2]), sigmf(a4[3]));
            } else {  // ACT_TANH_STABLE: pure stores only (no RMW)
                const float b0 = bcol[ni][0], b1 = bcol[ni][1];
                const float g0 = gcol[ni][0], g1 = gcol[ni][1];
#pragma unroll
                for (int h = 0; h < 2; h++) {
                    const int row = r0 + h * 8;
                    const size_t idx = (size_t)row * N + c0;
                    float p0 = tanhfast(a4[2 * h] + b0);
                    float p1 = tanhfast(a4[2 * h + 1] + b1);
                    float s0 = p0 * g0, s1 = p1 * g1;
                    *(__half2*)(Ch + idx) = __floats2half2_rn(p0, p1);
                    *(__half2*)(curout + idx) = __floats2half2_rn(s0, s1);
                    *(float2*)(sl + idx) = make_float2(s0, s1);
                }
            }
        }
    }
}

__global__ void __launch_bounds__(NTHR, 2) mma_gemm(
    const __half* __restrict__ A, const __half* __restrict__ W,
    const float* __restrict__ bias, float* __restrict__ Cf, __half* __restrict__ Ch,
    int N, int K, int act,
    const float* __restrict__ sigsc, __half* __restrict__ curout,
    float* __restrict__ sl)
{
    extern __shared__ char smemraw[];
    gemm_body(A, W, bias, Cf, Ch, N, K, act, sigsc, curout, sl,
              blockIdx.x, smem_u32(smemraw));
}

// merged dual-GEMM: blocks [0,nx1) -> problem 1, [nx1, nx1+nx2) -> problem 2
__global__ void __launch_bounds__(NTHR, 2) mma_gemm2(
    const __half* __restrict__ A1, const __half* __restrict__ W1,
    const float* __restrict__ bias1, float* __restrict__ Cf1,
    int N1, int K1, int act1, int nx1,
    const __half* __restrict__ A2, const __half* __restrict__ W2,
    const float* __restrict__ bias2, float* __restrict__ Cf2,
    int N2, int K2, int act2)
{
    extern __shared__ char smemraw[];
    const uint32_t sb = smem_u32(smemraw);
    if ((int)blockIdx.x < nx1)
        gemm_body(A1, W1, bias1, Cf1, nullptr, N1, K1, act1,
                  nullptr, nullptr, nullptr, blockIdx.x, sb);
    else
        gemm_body(A2, W2, bias2, Cf2, nullptr, N2, K2, act2,
                  nullptr, nullptr, nullptr, blockIdx.x - nx1, sb);
}

// ================= LayerNorm + GELU (step 2 only) =================
__global__ void __launch_bounds__(128) ln_gelu_kernel(
    const float* __restrict__ in, const float* __restrict__ g,
    const float* __restrict__ be, __half* __restrict__ outh, int N)
{
    const int row = blockIdx.x;
    const float4* x = (const float4*)(in + (size_t)row * N);
    const int nv = N >> 9;
    float4 v[4];
    float s = 0.f, ss = 0.f;
    for (int t = 0; t < nv; t++) {
        float4 w = x[threadIdx.x + (t << 7)];
        v[t] = w;
        s += w.x + w.y + w.z + w.w;
        ss += w.x * w.x + w.y * w.y + w.z * w.z + w.w * w.w;
    }
#pragma unroll
    for (int o = 16; o > 0; o >>= 1) {
        s += __shfl_down_sync(0xffffffff, s, o);
        ss += __shfl_down_sync(0xffffffff, ss, o);
    }
    __shared__ float sm[8];
    __shared__ float s_mean, s_rstd;
    const int w4 = threadIdx.x >> 5, lane = threadIdx.x & 31;
    if (lane == 0) { sm[w4] = s; sm[4 + w4] = ss; }
    __syncthreads();
    if (threadIdx.x == 0) {
        float S = sm[0] + sm[1] + sm[2] + sm[3];
        float SS = sm[4] + sm[5] + sm[6] + sm[7];
        float m = S / (float)N;
        s_mean = m;
        s_rstd = rsqrtf(SS / (float)N - m * m + 1e-5f);
    }
    __syncthreads();
    const float m = s_mean, r = s_rstd;
    const float k = 0.70710678118654752f;
    for (int t = 0; t < nv; t++) {
        const int c = (threadIdx.x + (t << 7)) << 2;
        float4 gg = *(const float4*)(g + c);
        float4 bb = *(const float4*)(be + c);
        float o0 = (v[t].x - m) * r * gg.x + bb.x;
        float o1 = (v[t].y - m) * r * gg.y + bb.y;
        float o2 = (v[t].z - m) * r * gg.z + bb.z;
        float o3 = (v[t].w - m) * r * gg.w + bb.w;
        o0 = 0.5f * o0 * (1.f + erff(o0 * k));
        o1 = 0.5f * o1 * (1.f + erff(o1 * k));
        o2 = 0.5f * o2 * (1.f + erff(o2 * k));
        o3 = 0.5f * o3 * (1.f + erff(o3 * k));
        const size_t idx = (size_t)row * N + c;
        *(__half2*)(outh + idx) = __floats2half2_rn(o0, o1);
        *(__half2*)(outh + idx + 2) = __floats2half2_rn(o2, o3);
    }
}

// ========== Dual LN: blocks [0,B) -> emo sigmoid-accum (N=1024, off 0);
//                     blocks [B,2B) -> ReLU->half (N=512, off 1024) ==========
__global__ void __launch_bounds__(128) ln_dual_kernel(
    const float* __restrict__ tmpc,
    const float* __restrict__ esg, const float* __restrict__ esbe,
    float* __restrict__ emo, int initFlag,
    const float* __restrict__ qgg, const float* __restrict__ qgbe,
    __half* __restrict__ tmph)
{
    const bool emoPart = (blockIdx.x < B_);
    const int row = emoPart ? blockIdx.x : blockIdx.x - B_;
    const int N = emoPart ? D_ : H_;
    const int off = emoPart ? 0 : D_;
    const float* g = emoPart ? esg : qgg;
    const float* be = emoPart ? esbe : qgbe;

    const float4* x = (const float4*)(tmpc + (size_t)row * NC_ + off);
    const int nv = N >> 9;
    float4 v[2];
    float s = 0.f, ss = 0.f;
    for (int t = 0; t < nv; t++) {
        float4 w = x[threadIdx.x + (t << 7)];
        v[t] = w;
        s += w.x + w.y + w.z + w.w;
        ss += w.x * w.x + w.y * w.y + w.z * w.z + w.w * w.w;
    }
#pragma unroll
    for (int o = 16; o > 0; o >>= 1) {
        s += __shfl_down_sync(0xffffffff, s, o);
        ss += __shfl_down_sync(0xffffffff, ss, o);
    }
    __shared__ float sm[8];
    __shared__ float s_mean, s_rstd;
    const int w4 = threadIdx.x >> 5, lane = threadIdx.x & 31;
    if (lane == 0) { sm[w4] = s; sm[4 + w4] = ss; }
    __syncthreads();
    if (threadIdx.x == 0) {
        float S = sm[0] + sm[1] + sm[2] + sm[3];
        float SS = sm[4] + sm[5] + sm[6] + sm[7];
        float m = S / (float)N;
        s_mean = m;
        s_rstd = rsqrtf(SS / (float)N - m * m + 1e-5f);
    }
    __syncthreads();
    const float m = s_mean, r = s_rstd;
    for (int t = 0; t < nv; t++) {
        const int c = (threadIdx.x + (t << 7)) << 2;
        float4 gg = *(const float4*)(g + c);
        float4 bb = *(const float4*)(be + c);
        float o0 = (v[t].x - m) * r * gg.x + bb.x;
        float o1 = (v[t].y - m) * r * gg.y + bb.y;
        float o2 = (v[t].z - m) * r * gg.z + bb.z;
        float o3 = (v[t].w - m) * r * gg.w + bb.w;
        const size_t idx = (size_t)row * N + c;
        if (emoPart) {
            float4 a;
            a.x = sigmf(o0); a.y = sigmf(o1); a.z = sigmf(o2); a.w = sigmf(o3);
            if (!initFlag) {
                float4 p = *(float4*)(emo + idx);
                a.x += p.x; a.y += p.y; a.z += p.z; a.w += p.w;
            }
            *(float4*)(emo + idx) = a;
        } else {
            o0 = fmaxf(o0, 0.f); o1 = fmaxf(o1, 0.f);
            o2 = fmaxf(o2, 0.f); o3 = fmaxf(o3, 0.f);
            *(__half2*)(tmph + idx) = __floats2half2_rn(o0, o1);
            *(__half2*)(tmph + idx + 2) = __floats2half2_rn(o2, o3);
        }
    }
}

// ========== fused init: seed->half, cmat, bcomb, sigsc, weight conversions ==
__global__ void __launch_bounds__(256) init_kernel(
    const float4* __restrict__ seed4, __half* __restrict__ cur,
    __half* __restrict__ cmat, float* __restrict__ bcomb,
    const float* __restrict__ esb, const float* __restrict__ qgb1,
    const float* __restrict__ sc, float* __restrict__ sigsc,
    const float4* __restrict__ s1, __half* __restrict__ d1, int n1v,
    const float4* __restrict__ s2, __half* __restrict__ d2, int n2v,
    const float* __restrict__ esw, const float* __restrict__ qgw1,
    __half* __restrict__ comb,
    const float4* __restrict__ s5, __half* __restrict__ d5, int n5v)
{
    const int stride = gridDim.x * 256;
    const int t0 = blockIdx.x * 256 + threadIdx.x;
    for (int i = t0; i < BD_ / 4; i += stride) {
        float4 v = seed4[i];
        *(__half2*)(cur + 4 * (size_t)i) = __floats2half2_rn(v.x, v.y);
        *(__half2*)(cur + 4 * (size_t)i + 2) = __floats2half2_rn(v.z, v.w);
    }
    for (int i = t0; i < D_ * D_; i += stride) {
        int k = i >> 10, n = i & (D_ - 1);
        int e = (n - k + D_) & (D_ - 1);
        cmat[i] = __float2half_rn(powf(0.9f, (float)e));
    }
    for (int i = t0; i < L_ * NC_; i += stride) {
        int l = i / NC_, c = i % NC_;
        bcomb[i] = (c < 1024) ? esb[l * 1024 + c] : qgb1[l * 512 + (c - 1024)];
    }
    for (int i = t0; i < L_ * D_; i += stride)
        sigsc[i] = 1.f / (1.f + expf(-sc[i]));
    for (int i = t0; i < n1v; i += stride) {
        float4 v = s1[i];
        *(__half2*)(d1 + 4 * (size_t)i) = __floats2half2_rn(v.x, v.y);
        *(__half2*)(d1 + 4 * (size_t)i + 2) = __floats2half2_rn(v.z, v.w);
    }
    for (int i = t0; i < n2v; i += stride) {
        float4 v = s2[i];
        *(__half2*)(d2 + 4 * (size_t)i) = __floats2half2_rn(v.x, v.y);
        *(__half2*)(d2 + 4 * (size_t)i + 2) = __floats2half2_rn(v.z, v.w);
    }
    for (int i = t0; i < n5v; i += stride) {
        float4 v = s5[i];
        *(__half2*)(d5 + 4 * (size_t)i) = __floats2half2_rn(v.x, v.y);
        *(__half2*)(d5 + 4 * (size_t)i + 2) = __floats2half2_rn(v.z, v.w);
    }
    const int ncomb4 = L_ * D_ * (NC_ / 4);
    for (int i = t0; i < ncomb4; i += stride) {
        int lk = i / (NC_ / 4);
        int n = (i % (NC_ / 4)) << 2;
        float4 v;
        if (n < 1024)
            v = *(const float4*)(esw + (size_t)lk * 1024 + n);
        else
            v = *(const float4*)(qgw1 + (size_t)lk * 512 + (n - 1024));
        __half* dst = comb + (size_t)lk * NC_ + n;
        *(__half2*)dst = __floats2half2_rn(v.x, v.y);
        *(__half2*)(dst + 2) = __floats2half2_rn(v.z, v.w);
    }
}

// ========== fused finalize + stability partial (reads 5 per-layer s arrays) =
__global__ void __launch_bounds__(256) finstab_kernel(
    const float4* __restrict__ s0a, const float4* __restrict__ s1a,
    const float4* __restrict__ s2a, const float4* __restrict__ s3a,
    const float4* __restrict__ s4a,
    const float4* __restrict__ es, float* __restrict__ out,
    __half* __restrict__ rcp, double* __restrict__ part)
{
    double acc = 0.0;
    for (int i = blockIdx.x * 256 + threadIdx.x; i < BD_ / 4; i += gridDim.x * 256) {
        float4 a = s0a[i], b = s1a[i], c = s2a[i], d = s3a[i], f = s4a[i];
        float4 e = es[i];
        float4 p, q;
        p.x = (((a.x + b.x) + c.x) + d.x) + f.x;
        p.y = (((a.y + b.y) + c.y) + d.y) + f.y;
        p.z = (((a.z + b.z) + c.z) + d.z) + f.z;
        p.w = (((a.w + b.w) + c.w) + d.w) + f.w;
        q.x = (((a.x * a.x + b.x * b.x) + c.x * c.x) + d.x * d.x) + f.x * f.x;
        q.y = (((a.y * a.y + b.y * b.y) + c.y * c.y) + d.y * d.y) + f.y * f.y;
        q.z = (((a.z * a.z + b.z * b.z) + c.z * c.z) + d.z * d.z) + f.z * f.z;
        q.w = (((a.w * a.w + b.w * b.w) + c.w * c.w) + d.w * d.w) + f.w * f.w;

        float4 cp = make_float4(p.x * 0.2f, p.y * 0.2f, p.z * 0.2f, p.w * 0.2f);
        *(float4*)(out + 4 * (size_t)i) = cp;
        *(float4*)(out + (size_t)BD_ + 4 * (size_t)i) =
            make_float4(e.x * 0.2f, e.y * 0.2f, e.z * 0.2f, e.w * 0.2f);
        *(__half2*)(rcp + 4 * (size_t)i) = __floats2half2_rn(cp.x, cp.y);
        *(__half2*)(rcp + 4 * (size_t)i + 2) = __floats2half2_rn(cp.z, cp.w);
        acc += (double)((q.x - p.x * p.x * 0.2f) * 0.25f);
        acc += (double)((q.y - p.y * p.y * 0.2f) * 0.25f);
        acc += (double)((q.z - p.z * p.z * 0.2f) * 0.25f);
        acc += (double)((q.w - p.w * p.w * 0.2f) * 0.25f);
    }
#pragma unroll
    for (int o = 16; o > 0; o >>= 1)
        acc += __shfl_down_sync(0xffffffff, acc, o);
    __shared__ double sm[8];
    int w = threadIdx.x >> 5, lane = threadIdx.x & 31;
    if (lane == 0) sm[w] = acc;
    __syncthreads();
    if (threadIdx.x == 0) {
        double t = 0.0;
        for (int i = 0; i < 8; i++) t += sm[i];
        part[blockIdx.x] = t;
    }
}

__global__ void __launch_bounds__(256) stab_final_kernel(const double* __restrict__ part,
                                                         float* __restrict__ out) {
    double acc = 0.0;
    for (int i = threadIdx.x; i < 1024; i += 256) acc += part[i];
#pragma unroll
    for (int o = 16; o > 0; o >>= 1)
        acc += __shfl_down_sync(0xffffffff, acc, o);
    __shared__ double sm[8];
    int w = threadIdx.x >> 5, lane = threadIdx.x & 31;
    if (lane == 0) sm[w] = acc;
    __syncthreads();
    if (threadIdx.x == 0) {
        double t = 0.0;
        for (int i = 0; i < 8; i++) t += sm[i];
        out[0] = (float)(1.0 - t / (double)BD_);
    }
}

// ================= host launch =================
static inline void launch_gemm(const __half* A, const __half* W, const float* bias,
                               float* Cf, __half* Ch, int N, int K, int act,
                               const float* sigsc, __half* curout, float* sl) {
    dim3 grid(N / NT, B_ / MT);
    mma_gemm<<<grid, NTHR, GEMM_SMEM>>>(A, W, bias, Cf, Ch, N, K, act,
                                        sigsc, curout, sl);
}

static inline void launch_gemm2(const __half* A1, const __half* W1, const float* b1,
                                float* C1, int N1, int K1, int act1,
                                const __half* A2, const __half* W2, const float* b2,
                                float* C2, int N2, int K2, int act2) {
    const int nx1 = N1 / NT, nx2 = N2 / NT;
    dim3 grid(nx1 + nx2, B_ / MT);
    mma_gemm2<<<grid, NTHR, GEMM_SMEM>>>(A1, W1, b1, C1, N1, K1, act1, nx1,
                                         A2, W2, b2, C2, N2, K2, act2);
}

extern "C" void kernel_launch(void* const* d_in, const int* in_sizes, int n_in,
                              void* d_out, int out_size)
{
    const float* seed = (const float*)d_in[0];
    const int o = (in_sizes[1] == 1) ? 2 : 1;
    const float* pg_w1 = (const float*)d_in[o + 0];
    const float* pg_b1 = (const float*)d_in[o + 1];
    const float* pg_g1 = (const float*)d_in[o + 2];
    const float* pg_be1 = (const float*)d_in[o + 3];
    const float* pg_w2 = (const float*)d_in[o + 4];
    const float* pg_b2 = (const float*)d_in[o + 5];
    const float* es_w = (const float*)d_in[o + 6];
    const float* es_b = (const float*)d_in[o + 7];
    const float* es_g = (const float*)d_in[o + 8];
    const float* es_be = (const float*)d_in[o + 9];
    const float* qg_w1 = (const float*)d_in[o + 10];
    const float* qg_b1 = (const float*)d_in[o + 11];
    const float* qg_g1 = (const float*)d_in[o + 12];
    const float* qg_be1 = (const float*)d_in[o + 13];
    const float* qg_w2 = (const float*)d_in[o + 14];
    const float* qg_b2 = (const float*)d_in[o + 15];
    const float* sc = (const float*)d_in[o + 16];
    float* out = (float*)d_out;

    __half *cur, *buf2dh, *pat, *tmph, *cmat, *rcp;
    __half *wpg1, *wpg2, *wcomb, *wqg2;
    float *buf2d, *tmpc, *emo, *sl, *bcomb, *sigsc;
    double* part;
    cudaGetSymbolAddress((void**)&cur, g_cur);
    cudaGetSymbolAddress((void**)&buf2d, g_buf2d);
    cudaGetSymbolAddress((void**)&buf2dh, g_buf2dh);
    cudaGetSymbolAddress((void**)&pat, g_pat);
    cudaGetSymbolAddress((void**)&tmpc, g_tmpc);
    cudaGetSymbolAddress((void**)&tmph, g_tmph);
    cudaGetSymbolAddress((void**)&emo, g_emo);
    cudaGetSymbolAddress((void**)&sl, g_sl);
    cudaGetSymbolAddress((void**)&cmat, g_cmat);
    cudaGetSymbolAddress((void**)&rcp, g_rcp);
    cudaGetSymbolAddress((void**)&part, g_part);
    cudaGetSymbolAddress((void**)&bcomb, g_bcomb);
    cudaGetSymbolAddress((void**)&sigsc, g_sigsc);
    cudaGetSymbolAddress((void**)&wpg1, g_wpg1);
    cudaGetSymbolAddress((void**)&wpg2, g_wpg2);
    cudaGetSymbolAddress((void**)&wcomb, g_wcomb);
    cudaGetSymbolAddress((void**)&wqg2, g_wqg2);

    cudaFuncSetAttribute(mma_gemm, cudaFuncAttributeMaxDynamicSharedMemorySize, GEMM_SMEM);
    cudaFuncSetAttribute(mma_gemm2, cudaFuncAttributeMaxDynamicSharedMemorySize, GEMM_SMEM);

    const size_t BD = (size_t)BD_;
    float* out_cf = out + 2 * BD;
    float* out_ss = out + 3 * BD;
    float* out_qa = out + 3 * BD + 1;

    init_kernel<<<4096, 256>>>(
        (const float4*)seed, cur, cmat, bcomb, es_b, qg_b1, sc, sigsc,
        (const float4*)pg_w1, wpg1, L_ * D_ * 2 * D_ / 4,
        (const float4*)pg_w2, wpg2, L_ * 2 * D_ * D_ / 4,
        es_w, qg_w1, wcomb,
        (const float4*)qg_w2, wqg2, L_ * H_ * D_ / 4);

    // layer-0 GEMM1 (standalone)
    launch_gemm(cur, wpg1, pg_b1, buf2d, nullptr, 2 * D_, D_, ACT_NONE,
                nullptr, nullptr, nullptr);

    for (int l = 0; l < L_; l++) {
        // 2) h = GELU(LN(pre1)) -> half
        ln_gelu_kernel<<<B_, 128>>>(buf2d, pg_g1 + (size_t)l * 2 * D_,
                                    pg_be1 + (size_t)l * 2 * D_, buf2dh, 2 * D_);
        // 3) pat = tanh(h @ pg_w2 + b2); stable -> cur (half) + sl[l] (fp32 store)
        launch_gemm(buf2dh, wpg2 + (size_t)l * 2 * D_ * D_, pg_b2 + (size_t)l * D_,
                    nullptr, pat, D_, 2 * D_, ACT_TANH_STABLE,
                    sigsc + (size_t)l * D_, cur, sl + (size_t)l * BD);
        // 4+6 merged) tmpc = pat @ [es_w|qg_w1] + [es_b|qg_b1]   [B,1536] float
        launch_gemm(pat, wcomb + (size_t)l * D_ * NC_, bcomb + (size_t)l * NC_,
                    tmpc, nullptr, NC_, D_, ACT_NONE, nullptr, nullptr, nullptr);
        // 5+7 merged) emo-LN (sigmoid accum) + ReLU-LN -> tmph, one launch
        ln_dual_kernel<<<2 * B_, 128>>>(tmpc,
                                        es_g + (size_t)l * D_, es_be + (size_t)l * D_,
                                        emo, (l == 0),
                                        qg_g1 + (size_t)l * H_, qg_be1 + (size_t)l * H_,
                                        tmph);
        if (l + 1 < L_) {
            // 8) anchors[l]  MERGED WITH  1) pre1 = cur @ pg_w1[l+1] + b1
            launch_gemm2(tmph, wqg2 + (size_t)l * H_ * D_, qg_b2 + (size_t)l * D_,
                         out_qa + (size_t)l * BD, D_, H_, ACT_NONE,
                         cur, wpg1 + (size_t)(l + 1) * D_ * 2 * D_,
                         pg_b1 + (size_t)(l + 1) * 2 * D_, buf2d,
                         2 * D_, D_, ACT_NONE);
        }
    }

    // finalize + stability partials (needs sl[4] from GEMM3(4) and emo)
    finstab_kernel<<<1024, 256>>>(
        (const float4*)(sl + 0 * BD), (const float4*)(sl + 1 * BD),
        (const float4*)(sl + 2 * BD), (const float4*)(sl + 3 * BD),
        (const float4*)(sl + 4 * BD),
        (const float4*)emo, out, rcp, part);
    // anchors[4] MERGED WITH coherence_field = sigmoid(rcp @ C)
    launch_gemm2(tmph, wqg2 + (size_t)4 * H_ * D_, qg_b2 + (size_t)4 * D_,
                 out_qa + (size_t)4 * BD, D_, H_, ACT_NONE,
                 rcp, cmat, nullptr, out_cf, D_, D_, ACT_SIGMOID);
    stab_final_kernel<<<1, 256>>>(part, out_ss);
    (void)n_in; (void)out_size;
}